// round 14
// baseline (speedup 1.0000x reference)
#include <cuda_runtime.h>
#include <cuda_bf16.h>
#include <cstdint>

// ============================================================================
// ResGatedGraphConv x3 + softmax. GEMMs on mma.sync bf16 (split-precision).
//   per layer: cat = A @ [Wk|Wq|Wv|Ws]^T + [bk|bq|bv|bias]  (one fused GEMM)
//              H[n] = skip[n] + sum_{j->n} sigmoid(K[n]+Q[j]) * V[j]
// Edge aggregation via per-call CSR (counting sort by dst) -> NO atomics.
// GEMM: 3-stage cp.async pipeline (96 KB smem), CTA 128x128, warp 64x64.
// ============================================================================

#define NMAX 20000
#define EMAX 400000

__device__ float         g_cat [NMAX * 1024];   // per-layer [N, 4D]: K|Q|V|H
__device__ __nv_bfloat16 g_Ahi [NMAX * 256];
__device__ __nv_bfloat16 g_Alo [NMAX * 256];
__device__ __nv_bfloat16 g_Whi [1024 * 256];    // [Ncat, K] K-major
__device__ __nv_bfloat16 g_Wlo [1024 * 256];
__device__ float         g_bias[1024];
__device__ int           g_is64;
__device__ int           g_off [NMAX + 1];
__device__ int           g_cur [NMAX];
__device__ int           g_srcs[EMAX];

__device__ __forceinline__ uint32_t smem_u32(const void* p) {
    uint32_t a;
    asm("{ .reg .u64 t; cvta.to.shared.u64 t, %1; cvt.u32.u64 %0, t; }" : "=r"(a) : "l"(p));
    return a;
}

__device__ __forceinline__ void ldsm_x4(uint32_t* r, uint32_t addr) {
    asm volatile("ldmatrix.sync.aligned.m8n8.x4.shared.b16 {%0,%1,%2,%3}, [%4];"
                 : "=r"(r[0]), "=r"(r[1]), "=r"(r[2]), "=r"(r[3]) : "r"(addr));
}

__device__ __forceinline__ void mma16816(float* c, const uint32_t* a,
                                         uint32_t b0, uint32_t b1) {
    asm volatile(
        "mma.sync.aligned.m16n8k16.row.col.f32.bf16.bf16.f32 "
        "{%0,%1,%2,%3}, {%4,%5,%6,%7}, {%8,%9}, {%0,%1,%2,%3};"
        : "+f"(c[0]), "+f"(c[1]), "+f"(c[2]), "+f"(c[3])
        : "r"(a[0]), "r"(a[1]), "r"(a[2]), "r"(a[3]), "r"(b0), "r"(b1));
}

#define CP_ASYNC16(dst, src, sz) \
    asm volatile("cp.async.cg.shared.global [%0], [%1], 16, %2;" \
                 :: "r"(dst), "l"(src), "r"(sz))
#define CP_COMMIT()  asm volatile("cp.async.commit_group;" ::: "memory")
#define CP_WAIT0()   asm volatile("cp.async.wait_group 0;" ::: "memory")
#define CP_WAIT1()   asm volatile("cp.async.wait_group 1;" ::: "memory")

// ----------------------------------------------------------------------------
// edge_index dtype detection (int64 high words all-zero for node ids < 2^31)
// ----------------------------------------------------------------------------
__global__ void detect_i64(const unsigned int* __restrict__ p) {
    __shared__ unsigned int s;
    if (threadIdx.x == 0) s = 0u;
    __syncthreads();
    unsigned int v = 0u;
    for (int i = threadIdx.x; i < 2048; i += blockDim.x) v |= p[2 * i + 1];
    atomicOr(&s, v);
    __syncthreads();
    if (threadIdx.x == 0) g_is64 = (s == 0u) ? 1 : 0;
}

// ----------------------------------------------------------------------------
// CSR build: zero counters -> in-degree histogram -> scan -> scatter srcs
// ----------------------------------------------------------------------------
__global__ void zero_i(int* __restrict__ p, int n) {
    int i = blockIdx.x * blockDim.x + threadIdx.x;
    if (i < n) p[i] = 0;
}

__global__ void build_hist(const void* __restrict__ ei_raw, int* __restrict__ deg, int E) {
    int e = blockIdx.x * blockDim.x + threadIdx.x;
    if (e >= E) return;
    int dst = g_is64 ? (int)((const long long*)ei_raw)[E + e]
                     : ((const int*)ei_raw)[E + e];
    atomicAdd(&deg[dst], 1);
}

// single-block hierarchical scan: per-thread serial + warp shfl + cross-warp
#define SCAN_MAXPER 32
__global__ void scan_off(const int* __restrict__ deg, int* __restrict__ off,
                         int* __restrict__ cur, int Nn) {
    __shared__ int warpTot[32];
    const int t    = threadIdx.x;
    const int lane = t & 31;
    const int wrp  = t >> 5;
    const int per  = (Nn + 1023) / 1024;
    const int base = t * per;

    int vals[SCAN_MAXPER];
    int sum = 0;
#pragma unroll 8
    for (int i = 0; i < per; i++) {
        int j = base + i;
        vals[i] = (j < Nn) ? deg[j] : 0;
        sum += vals[i];
    }

    // inclusive warp scan of sum
    int inc = sum;
#pragma unroll
    for (int o = 1; o < 32; o <<= 1) {
        int v = __shfl_up_sync(0xffffffffu, inc, o);
        if (lane >= o) inc += v;
    }
    if (lane == 31) warpTot[wrp] = inc;
    __syncthreads();
    if (wrp == 0) {
        int v = warpTot[lane];
        int wi = v;
#pragma unroll
        for (int o = 1; o < 32; o <<= 1) {
            int u = __shfl_up_sync(0xffffffffu, wi, o);
            if (lane >= o) wi += u;
        }
        warpTot[lane] = wi - v;   // exclusive warp base
    }
    __syncthreads();

    int run = warpTot[wrp] + (inc - sum);   // exclusive prefix for this thread
#pragma unroll 8
    for (int i = 0; i < per; i++) {
        int j = base + i;
        if (j < Nn) {
            off[j] = run;
            cur[j] = run;
            run += vals[i];
        }
    }
    if (t == 1023) off[Nn] = run;
}

__global__ void build_csr(const void* __restrict__ ei_raw, int* __restrict__ cur,
                          int* __restrict__ srcs, int E) {
    int e = blockIdx.x * blockDim.x + threadIdx.x;
    if (e >= E) return;
    int src, dst;
    if (g_is64) {
        const long long* ei = (const long long*)ei_raw;
        src = (int)ei[e];
        dst = (int)ei[E + e];
    } else {
        const int* ei = (const int*)ei_raw;
        src = ei[e];
        dst = ei[E + e];
    }
    int pos = atomicAdd(&cur[dst], 1);
    srcs[pos] = src;
}

// ----------------------------------------------------------------------------
// Activation convert (layer 1 only): fp32 -> bf16 hi/lo
// ----------------------------------------------------------------------------
__global__ void conv_a(const float* __restrict__ src,
                       __nv_bfloat16* __restrict__ hi, __nv_bfloat16* __restrict__ lo,
                       int total)
{
    int idx = blockIdx.x * blockDim.x + threadIdx.x;
    if (idx >= total) return;
    float a = src[idx];
    __nv_bfloat16 h = __float2bfloat16(a);
    hi[idx] = h;
    lo[idx] = __float2bfloat16(a - __bfloat162float(h));
}

// ----------------------------------------------------------------------------
// Weight convert: 4x W [K, D] fp32 -> transposed concat [Ncat=4D, K] bf16 hi/lo
// ----------------------------------------------------------------------------
__global__ void conv_w(const float* __restrict__ W0, const float* __restrict__ W1,
                       const float* __restrict__ W2, const float* __restrict__ W3,
                       const float* __restrict__ b0, const float* __restrict__ b1,
                       const float* __restrict__ b2, const float* __restrict__ b3,
                       __nv_bfloat16* __restrict__ hi, __nv_bfloat16* __restrict__ lo,
                       float* __restrict__ biascat, int K, int D)
{
    int idx = blockIdx.x * blockDim.x + threadIdx.x;
    int Ncat = 4 * D;
    if (idx >= Ncat * K) return;
    int n = idx / K, k = idx - n * K;
    int z = n / D, jz = n - z * D;
    const float* W = (z == 0) ? W0 : (z == 1) ? W1 : (z == 2) ? W2 : W3;
    float w = W[(size_t)k * D + jz];
    __nv_bfloat16 h = __float2bfloat16(w);
    hi[idx] = h;
    lo[idx] = __float2bfloat16(w - __bfloat162float(h));
    if (k == 0) {
        const float* b = (z == 0) ? b0 : (z == 1) ? b1 : (z == 2) ? b2 : b3;
        biascat[n] = b[jz];
    }
}

// ----------------------------------------------------------------------------
// mma.sync GEMM: cat[M, Ncat] = Ahi@Whi^T + Ahi@Wlo^T + Alo@Whi^T + bias
//   128 threads / 4 warps (2x2), CTA 128x128, warp 64x64, BK=64,
//   XOR-swizzled smem, 3-stage cp.async pipeline (dynamic smem 96 KB).
// ----------------------------------------------------------------------------
#define STAGE_BYTES 16384          // 128 rows * 128 B
#define NSTAGE 3
#define ABUF_BYTES  (NSTAGE * STAGE_BYTES)

__global__ __launch_bounds__(128)
void gemm_mma(const __nv_bfloat16* __restrict__ Ahi, const __nv_bfloat16* __restrict__ Alo,
              const __nv_bfloat16* __restrict__ Whi, const __nv_bfloat16* __restrict__ Wlo,
              const float* __restrict__ biascat, float* __restrict__ C,
              int M, int K, int Ncat)
{
    extern __shared__ __align__(1024) char dynsmem[];

    const int tid  = threadIdx.x;
    const int wid  = tid >> 5;
    const int lane = tid & 31;
    const int wr   = wid & 1;
    const int wc   = wid >> 1;
    const int rowBase = blockIdx.x * 128;
    const int colBase = blockIdx.y * 128;

    const uint32_t sBase = smem_u32(dynsmem);

    const int aRowL = (lane & 15);
    const int aSegH = (lane >> 4);
    const int grp   = lane >> 3;
    const int bRowL = (grp >> 1) * 8 + (lane & 7);
    const int bSegH = (grp & 1);

    float acc[4][8][4];
#pragma unroll
    for (int mi = 0; mi < 4; mi++)
#pragma unroll
        for (int nj = 0; nj < 8; nj++)
#pragma unroll
            for (int q = 0; q < 4; q++) acc[mi][nj][q] = 0.f;

    const int chunks = 3 * (K >> 6);

    auto issue = [&](int stage, int p, int kc) {
        const __nv_bfloat16* __restrict__ As = (p == 2) ? Alo : Ahi;
        const __nv_bfloat16* __restrict__ Ws = (p == 1) ? Wlo : Whi;
        const int kOff = kc << 6;
        const uint32_t aSt = sBase + stage * STAGE_BYTES;
        const uint32_t wSt = sBase + ABUF_BYTES + stage * STAGE_BYTES;
#pragma unroll
        for (int it = 0; it < 8; it++) {
            int idx  = it * 128 + tid;
            int r    = idx >> 3;
            int kseg = idx & 7;
            uint32_t doff = (uint32_t)(r * 128 + ((kseg ^ (r & 7)) << 4));
            int grow = rowBase + r;
            const __nv_bfloat16* asrc = &As[(size_t)(grow < M ? grow : 0) * K + kOff + kseg * 8];
            CP_ASYNC16(aSt + doff, asrc, (grow < M) ? 16 : 0);
            CP_ASYNC16(wSt + doff, &Ws[(size_t)(colBase + r) * K + kOff + kseg * 8], 16);
        }
        CP_COMMIT();
    };

    issue(0, 0, 0);
    if (chunks > 1) issue(1, 1 % 3, 1 / 3);

    for (int ch = 0; ch < chunks; ch++) {
        // ensure stage ch is loaded (leave at most 1 group in flight)
        if (ch + 1 < chunks) { CP_WAIT1(); } else { CP_WAIT0(); }
        __syncthreads();

        // issue chunk ch+2 into stage (ch+2)%3 (contents consumed at ch-1)
        if (ch + 2 < chunks) {
            const int nc = ch + 2;
            issue(nc % NSTAGE, nc % 3, nc / 3);
        }

        const int st = ch % NSTAGE;
        const uint32_t aBase = sBase + st * STAGE_BYTES;
        const uint32_t bBase = sBase + ABUF_BYTES + st * STAGE_BYTES;
#pragma unroll
        for (int ks = 0; ks < 4; ks++) {
            uint32_t a[4][4];
#pragma unroll
            for (int mi = 0; mi < 4; mi++) {
                int r = wr * 64 + mi * 16 + aRowL;
                uint32_t seg = (uint32_t)((ks * 2 + aSegH) ^ (r & 7));
                ldsm_x4(a[mi], aBase + (uint32_t)(r * 128) + (seg << 4));
            }
#pragma unroll
            for (int nj2 = 0; nj2 < 4; nj2++) {
                uint32_t b[4];
                int r = wc * 64 + nj2 * 16 + bRowL;
                uint32_t seg = (uint32_t)((ks * 2 + bSegH) ^ (r & 7));
                ldsm_x4(b, bBase + (uint32_t)(r * 128) + (seg << 4));
#pragma unroll
                for (int mi = 0; mi < 4; mi++) {
                    mma16816(acc[mi][nj2 * 2 + 0], a[mi], b[0], b[1]);
                    mma16816(acc[mi][nj2 * 2 + 1], a[mi], b[2], b[3]);
                }
            }
        }
        __syncthreads();   // all warps done with stage ch before it is refilled
    }

    // ---- epilogue: +bias, store ----
    const int rBase0 = rowBase + wr * 64 + (lane >> 2);
    const int cBase  = colBase + wc * 64 + ((lane & 3) << 1);
#pragma unroll
    for (int mi = 0; mi < 4; mi++) {
        int r0 = rBase0 + mi * 16;
        int r1 = r0 + 8;
#pragma unroll
        for (int nj = 0; nj < 8; nj++) {
            int col = cBase + nj * 8;
            float2 b2 = *(const float2*)&biascat[col];
            if (r0 < M) {
                float2 o = make_float2(acc[mi][nj][0] + b2.x, acc[mi][nj][1] + b2.y);
                *(float2*)&C[(size_t)r0 * Ncat + col] = o;
            }
            if (r1 < M) {
                float2 o = make_float2(acc[mi][nj][2] + b2.x, acc[mi][nj][3] + b2.y);
                *(float2*)&C[(size_t)r1 * Ncat + col] = o;
            }
        }
    }
}

// ----------------------------------------------------------------------------
// CSR aggregation, no atomics. thread = (dst node, float4 chunk).
//   acc = skip[n] (cat +3D); for each in-edge j: acc += sigmoid(k[n]+q[j])*v[j]
//   store H; optionally emit bf16 hi/lo for next layer's GEMM input.
// ----------------------------------------------------------------------------
__global__ void edge_agg(const int* __restrict__ off, const int* __restrict__ srcs,
                         float* __restrict__ cat,
                         __nv_bfloat16* __restrict__ hiOut, __nv_bfloat16* __restrict__ loOut,
                         int Nn, int D, int stride, int cshift)
{
    int idx = blockIdx.x * blockDim.x + threadIdx.x;
    int total = Nn << cshift;
    if (idx >= total) return;
    int n = idx >> cshift;
    int c = (idx & ((1 << cshift) - 1)) << 2;
    const int D2 = 2 * D, D3 = 3 * D;

    const float4 k = *(const float4*)&cat[(size_t)n * stride + c];
    float4 acc     = *(const float4*)&cat[(size_t)n * stride + D3 + c];

    const int s0 = off[n], s1 = off[n + 1];
#pragma unroll 2
    for (int i = s0; i < s1; i++) {
        int s = srcs[i];
        const float4 q = *(const float4*)&cat[(size_t)s * stride + D + c];
        const float4 v = *(const float4*)&cat[(size_t)s * stride + D2 + c];
        acc.x += v.x / (1.f + __expf(-(k.x + q.x)));
        acc.y += v.y / (1.f + __expf(-(k.y + q.y)));
        acc.z += v.z / (1.f + __expf(-(k.z + q.z)));
        acc.w += v.w / (1.f + __expf(-(k.w + q.w)));
    }

    *(float4*)&cat[(size_t)n * stride + D3 + c] = acc;

    if (hiOut) {
        __nv_bfloat16 h[4], l[4];
        const float* af = (const float*)&acc;
#pragma unroll
        for (int j = 0; j < 4; j++) {
            h[j] = __float2bfloat16(af[j]);
            l[j] = __float2bfloat16(af[j] - __bfloat162float(h[j]));
        }
        *(uint2*)&hiOut[(size_t)n * D + c] = *(const uint2*)h;
        *(uint2*)&loOut[(size_t)n * D + c] = *(const uint2*)l;
    }
}

// ----------------------------------------------------------------------------
// Row softmax over 64 cols (strided source): one warp per row.
// ----------------------------------------------------------------------------
__global__ void softmax64(const float* __restrict__ H, int stride, int offc,
                          float* __restrict__ out, int M)
{
    int warp = threadIdx.x >> 5;
    int lane = threadIdx.x & 31;
    int row  = blockIdx.x * (blockDim.x >> 5) + warp;
    if (row >= M) return;
    float a = H[(size_t)row * stride + offc + lane];
    float b = H[(size_t)row * stride + offc + 32 + lane];
    float mx = fmaxf(a, b);
#pragma unroll
    for (int o = 16; o > 0; o >>= 1) mx = fmaxf(mx, __shfl_xor_sync(0xffffffffu, mx, o));
    float ea = __expf(a - mx);
    float eb = __expf(b - mx);
    float s  = ea + eb;
#pragma unroll
    for (int o = 16; o > 0; o >>= 1) s += __shfl_xor_sync(0xffffffffu, s, o);
    float inv = 1.f / s;
    out[row * 64 + lane]      = ea * inv;
    out[row * 64 + 32 + lane] = eb * inv;
}

// ----------------------------------------------------------------------------
extern "C" void kernel_launch(void* const* d_in, const int* in_sizes, int n_in,
                              void* d_out, int out_size)
{
    const float* x  = (const float*)d_in[0];
    const void*  ei = d_in[1];
    const int Nn = in_sizes[0] / 256;
    const int E  = in_sizes[1] / 2;

    float *pCat, *pBias;
    __nv_bfloat16 *pAhi, *pAlo, *pWhi, *pWlo;
    int *pOff, *pCur, *pSrcs;
    cudaGetSymbolAddress((void**)&pCat,  g_cat);
    cudaGetSymbolAddress((void**)&pAhi,  g_Ahi);
    cudaGetSymbolAddress((void**)&pAlo,  g_Alo);
    cudaGetSymbolAddress((void**)&pWhi,  g_Whi);
    cudaGetSymbolAddress((void**)&pWlo,  g_Wlo);
    cudaGetSymbolAddress((void**)&pBias, g_bias);
    cudaGetSymbolAddress((void**)&pOff,  g_off);
    cudaGetSymbolAddress((void**)&pCur,  g_cur);
    cudaGetSymbolAddress((void**)&pSrcs, g_srcs);

    const float* w[26];
    for (int i = 2; i < 26; i++) w[i] = (const float*)d_in[i];

    const int gm = (Nn + 127) / 128;
    const int SMEM = 2 * ABUF_BYTES;   // 96 KB
    cudaFuncSetAttribute(gemm_mma, cudaFuncAttributeMaxDynamicSharedMemorySize, SMEM);

    // ---- CSR build (once per call, reused by all 3 layers) ----
    detect_i64<<<1, 256>>>((const unsigned int*)ei);
    zero_i<<<(Nn + 255) / 256, 256>>>(pCur, Nn);
    build_hist<<<(E + 255) / 256, 256>>>(ei, pCur, E);
    scan_off<<<1, 1024>>>(pCur, pOff, pCur, Nn);   // cur becomes cursors
    build_csr<<<(E + 255) / 256, 256>>>(ei, pCur, pSrcs, E);

    // ---- layer 1: K=256, D=256, Ncat=1024 ----
    conv_w<<<(1024 * 256 + 255) / 256, 256>>>(
        w[2], w[4], w[6], w[20], w[3], w[5], w[7], w[21],
        pWhi, pWlo, pBias, 256, 256);
    conv_a<<<(Nn * 256 + 255) / 256, 256>>>(x, pAhi, pAlo, Nn * 256);
    gemm_mma<<<dim3(gm, 8), 128, SMEM>>>(pAhi, pAlo, pWhi, pWlo, pBias, pCat, Nn, 256, 1024);
    edge_agg<<<((Nn << 6) + 255) / 256, 256>>>(pOff, pSrcs, pCat, pAhi, pAlo, Nn, 256, 1024, 6);

    // ---- layer 2: K=256, D=128, Ncat=512 ----
    conv_w<<<(512 * 256 + 255) / 256, 256>>>(
        w[8], w[10], w[12], w[22], w[9], w[11], w[13], w[23],
        pWhi, pWlo, pBias, 256, 128);
    gemm_mma<<<dim3(gm, 4), 128, SMEM>>>(pAhi, pAlo, pWhi, pWlo, pBias, pCat, Nn, 256, 512);
    edge_agg<<<((Nn << 5) + 255) / 256, 256>>>(pOff, pSrcs, pCat, pAhi, pAlo, Nn, 128, 512, 5);

    // ---- layer 3: K=128, D=64, Ncat=256 ----
    conv_w<<<(256 * 128 + 255) / 256, 256>>>(
        w[14], w[16], w[18], w[24], w[15], w[17], w[19], w[25],
        pWhi, pWlo, pBias, 128, 64);
    gemm_mma<<<dim3(gm, 2), 128, SMEM>>>(pAhi, pAlo, pWhi, pWlo, pBias, pCat, Nn, 128, 256);
    edge_agg<<<((Nn << 4) + 255) / 256, 256>>>(pOff, pSrcs, pCat, nullptr, nullptr, Nn, 64, 256, 4);

    softmax64<<<(Nn + 7) / 8, 256>>>(pCat, 256, 192, (float*)d_out, Nn);
}

// round 15
// speedup vs baseline: 1.0492x; 1.0492x over previous
#include <cuda_runtime.h>
#include <cuda_bf16.h>
#include <cstdint>

// ============================================================================
// ResGatedGraphConv x3 + softmax. GEMMs on mma.sync bf16 (split-precision).
//   per layer: cat = A @ [Wk|Wq|Wv|Ws]^T + [bk|bq|bv|bias]  (one fused GEMM)
//              H[n] = skip[n] + sum_{j->n} sigmoid(K[n]+Q[j]) * V[j]
// Edge aggregation via per-call CSR (counting sort by dst) -> NO atomics.
// GEMM: 2-stage cp.async pipeline (64 KB smem), CTA 128x128, warp 64x64.
// CSR scan: 3-pass multi-block coalesced scan (the 1-block strided scan
// measured 26.6 us regardless of barrier structure -> memory-pattern bound).
// ============================================================================

#define NMAX 20000
#define EMAX 400000

__device__ float         g_cat [NMAX * 1024];   // per-layer [N, 4D]: K|Q|V|H
__device__ __nv_bfloat16 g_Ahi [NMAX * 256];
__device__ __nv_bfloat16 g_Alo [NMAX * 256];
__device__ __nv_bfloat16 g_Whi [1024 * 256];    // [Ncat, K] K-major
__device__ __nv_bfloat16 g_Wlo [1024 * 256];
__device__ float         g_bias[1024];
__device__ int           g_is64;
__device__ int           g_off [NMAX + 1];
__device__ int           g_cur [NMAX];
__device__ int           g_srcs[EMAX];
__device__ int           g_bsum[64];

__device__ __forceinline__ uint32_t smem_u32(const void* p) {
    uint32_t a;
    asm("{ .reg .u64 t; cvta.to.shared.u64 t, %1; cvt.u32.u64 %0, t; }" : "=r"(a) : "l"(p));
    return a;
}

__device__ __forceinline__ void ldsm_x4(uint32_t* r, uint32_t addr) {
    asm volatile("ldmatrix.sync.aligned.m8n8.x4.shared.b16 {%0,%1,%2,%3}, [%4];"
                 : "=r"(r[0]), "=r"(r[1]), "=r"(r[2]), "=r"(r[3]) : "r"(addr));
}

__device__ __forceinline__ void mma16816(float* c, const uint32_t* a,
                                         uint32_t b0, uint32_t b1) {
    asm volatile(
        "mma.sync.aligned.m16n8k16.row.col.f32.bf16.bf16.f32 "
        "{%0,%1,%2,%3}, {%4,%5,%6,%7}, {%8,%9}, {%0,%1,%2,%3};"
        : "+f"(c[0]), "+f"(c[1]), "+f"(c[2]), "+f"(c[3])
        : "r"(a[0]), "r"(a[1]), "r"(a[2]), "r"(a[3]), "r"(b0), "r"(b1));
}

#define CP_ASYNC16(dst, src, sz) \
    asm volatile("cp.async.cg.shared.global [%0], [%1], 16, %2;" \
                 :: "r"(dst), "l"(src), "r"(sz))
#define CP_COMMIT()  asm volatile("cp.async.commit_group;" ::: "memory")
#define CP_WAIT0()   asm volatile("cp.async.wait_group 0;" ::: "memory")

// ----------------------------------------------------------------------------
// edge_index dtype detection (int64 high words all-zero for node ids < 2^31)
// ----------------------------------------------------------------------------
__global__ void detect_i64(const unsigned int* __restrict__ p) {
    __shared__ unsigned int s;
    if (threadIdx.x == 0) s = 0u;
    __syncthreads();
    unsigned int v = 0u;
    for (int i = threadIdx.x; i < 2048; i += blockDim.x) v |= p[2 * i + 1];
    atomicOr(&s, v);
    __syncthreads();
    if (threadIdx.x == 0) g_is64 = (s == 0u) ? 1 : 0;
}

// ----------------------------------------------------------------------------
// CSR build: zero -> histogram -> 3-pass coalesced scan -> scatter srcs
// ----------------------------------------------------------------------------
__global__ void zero_i(int* __restrict__ p, int n) {
    int i = blockIdx.x * blockDim.x + threadIdx.x;
    if (i < n) p[i] = 0;
}

__global__ void build_hist(const void* __restrict__ ei_raw, int* __restrict__ deg, int E) {
    int e = blockIdx.x * blockDim.x + threadIdx.x;
    if (e >= E) return;
    int dst = g_is64 ? (int)((const long long*)ei_raw)[E + e]
                     : ((const int*)ei_raw)[E + e];
    atomicAdd(&deg[dst], 1);
}

// pass 1: per-block (1024 elems) sum, coalesced
__global__ void scan_p1(const int* __restrict__ deg, int* __restrict__ bsum, int Nn) {
    __shared__ int wsum[32];
    int g = blockIdx.x * 1024 + threadIdx.x;
    int v = (g < Nn) ? deg[g] : 0;
    int s = v;
#pragma unroll
    for (int o = 16; o > 0; o >>= 1) s += __shfl_xor_sync(0xffffffffu, s, o);
    if ((threadIdx.x & 31) == 0) wsum[threadIdx.x >> 5] = s;
    __syncthreads();
    if (threadIdx.x < 32) {
        int t = wsum[threadIdx.x];
#pragma unroll
        for (int o = 16; o > 0; o >>= 1) t += __shfl_xor_sync(0xffffffffu, t, o);
        if (threadIdx.x == 0) bsum[blockIdx.x] = t;
    }
}

// pass 2: one warp scans block sums -> exclusive bases; also writes off[Nn]
__global__ void scan_p2(int* __restrict__ bsum, int* __restrict__ off,
                        int nb, int Nn) {
    int lane = threadIdx.x;
    int v = (lane < nb) ? bsum[lane] : 0;
    int inc = v;
#pragma unroll
    for (int o = 1; o < 32; o <<= 1) {
        int u = __shfl_up_sync(0xffffffffu, inc, o);
        if (lane >= o) inc += u;
    }
    if (lane < nb) bsum[lane] = inc - v;   // exclusive base
    if (lane == 31) off[Nn] = inc;         // total (= E)
}

// pass 3: per-block inclusive scan + base, coalesced writes to off & cur
__global__ void scan_p3(const int* __restrict__ deg, const int* __restrict__ bsum,
                        int* __restrict__ off, int* __restrict__ cur, int Nn) {
    __shared__ int wtot[32];
    int g = blockIdx.x * 1024 + threadIdx.x;
    int lane = threadIdx.x & 31;
    int wrp  = threadIdx.x >> 5;
    int v = (g < Nn) ? deg[g] : 0;
    int inc = v;
#pragma unroll
    for (int o = 1; o < 32; o <<= 1) {
        int u = __shfl_up_sync(0xffffffffu, inc, o);
        if (lane >= o) inc += u;
    }
    if (lane == 31) wtot[wrp] = inc;
    __syncthreads();
    if (wrp == 0) {
        int t = (lane < 32) ? wtot[lane] : 0;
        int wi = t;
#pragma unroll
        for (int o = 1; o < 32; o <<= 1) {
            int u = __shfl_up_sync(0xffffffffu, wi, o);
            if (lane >= o) wi += u;
        }
        wtot[lane] = wi - t;
    }
    __syncthreads();
    if (g < Nn) {
        int ex = bsum[blockIdx.x] + wtot[wrp] + inc - v;
        off[g] = ex;
        cur[g] = ex;
    }
}

__global__ void build_csr(const void* __restrict__ ei_raw, int* __restrict__ cur,
                          int* __restrict__ srcs, int E) {
    int e = blockIdx.x * blockDim.x + threadIdx.x;
    if (e >= E) return;
    int src, dst;
    if (g_is64) {
        const long long* ei = (const long long*)ei_raw;
        src = (int)ei[e];
        dst = (int)ei[E + e];
    } else {
        const int* ei = (const int*)ei_raw;
        src = ei[e];
        dst = ei[E + e];
    }
    int pos = atomicAdd(&cur[dst], 1);
    srcs[pos] = src;
}

// ----------------------------------------------------------------------------
// Activation convert (layer 1 only): fp32 -> bf16 hi/lo
// ----------------------------------------------------------------------------
__global__ void conv_a(const float* __restrict__ src,
                       __nv_bfloat16* __restrict__ hi, __nv_bfloat16* __restrict__ lo,
                       int total)
{
    int idx = blockIdx.x * blockDim.x + threadIdx.x;
    if (idx >= total) return;
    float a = src[idx];
    __nv_bfloat16 h = __float2bfloat16(a);
    hi[idx] = h;
    lo[idx] = __float2bfloat16(a - __bfloat162float(h));
}

// ----------------------------------------------------------------------------
// Weight convert: 4x W [K, D] fp32 -> transposed concat [Ncat=4D, K] bf16 hi/lo
// ----------------------------------------------------------------------------
__global__ void conv_w(const float* __restrict__ W0, const float* __restrict__ W1,
                       const float* __restrict__ W2, const float* __restrict__ W3,
                       const float* __restrict__ b0, const float* __restrict__ b1,
                       const float* __restrict__ b2, const float* __restrict__ b3,
                       __nv_bfloat16* __restrict__ hi, __nv_bfloat16* __restrict__ lo,
                       float* __restrict__ biascat, int K, int D)
{
    int idx = blockIdx.x * blockDim.x + threadIdx.x;
    int Ncat = 4 * D;
    if (idx >= Ncat * K) return;
    int n = idx / K, k = idx - n * K;
    int z = n / D, jz = n - z * D;
    const float* W = (z == 0) ? W0 : (z == 1) ? W1 : (z == 2) ? W2 : W3;
    float w = W[(size_t)k * D + jz];
    __nv_bfloat16 h = __float2bfloat16(w);
    hi[idx] = h;
    lo[idx] = __float2bfloat16(w - __bfloat162float(h));
    if (k == 0) {
        const float* b = (z == 0) ? b0 : (z == 1) ? b1 : (z == 2) ? b2 : b3;
        biascat[n] = b[jz];
    }
}

// ----------------------------------------------------------------------------
// mma.sync GEMM: cat[M, Ncat] = Ahi@Whi^T + Ahi@Wlo^T + Alo@Whi^T + bias
//   128 threads / 4 warps (2x2), CTA 128x128, warp 64x64, BK=64,
//   XOR-swizzled smem, 2-stage cp.async pipeline (dynamic smem 64 KB).
// ----------------------------------------------------------------------------
#define STAGE_BYTES 16384          // 128 rows * 128 B
#define ABUF_BYTES  (2 * STAGE_BYTES)

__global__ __launch_bounds__(128)
void gemm_mma(const __nv_bfloat16* __restrict__ Ahi, const __nv_bfloat16* __restrict__ Alo,
              const __nv_bfloat16* __restrict__ Whi, const __nv_bfloat16* __restrict__ Wlo,
              const float* __restrict__ biascat, float* __restrict__ C,
              int M, int K, int Ncat)
{
    extern __shared__ __align__(1024) char dynsmem[];

    const int tid  = threadIdx.x;
    const int wid  = tid >> 5;
    const int lane = tid & 31;
    const int wr   = wid & 1;
    const int wc   = wid >> 1;
    const int rowBase = blockIdx.x * 128;
    const int colBase = blockIdx.y * 128;

    const uint32_t sBase = smem_u32(dynsmem);

    const int aRowL = (lane & 15);
    const int aSegH = (lane >> 4);
    const int grp   = lane >> 3;
    const int bRowL = (grp >> 1) * 8 + (lane & 7);
    const int bSegH = (grp & 1);

    float acc[4][8][4];
#pragma unroll
    for (int mi = 0; mi < 4; mi++)
#pragma unroll
        for (int nj = 0; nj < 8; nj++)
#pragma unroll
            for (int q = 0; q < 4; q++) acc[mi][nj][q] = 0.f;

    const int chunks = 3 * (K >> 6);

    auto issue = [&](int stage, int p, int kc) {
        const __nv_bfloat16* __restrict__ As = (p == 2) ? Alo : Ahi;
        const __nv_bfloat16* __restrict__ Ws = (p == 1) ? Wlo : Whi;
        const int kOff = kc << 6;
        const uint32_t aSt = sBase + stage * STAGE_BYTES;
        const uint32_t wSt = sBase + ABUF_BYTES + stage * STAGE_BYTES;
#pragma unroll
        for (int it = 0; it < 8; it++) {
            int idx  = it * 128 + tid;
            int r    = idx >> 3;
            int kseg = idx & 7;
            uint32_t doff = (uint32_t)(r * 128 + ((kseg ^ (r & 7)) << 4));
            int grow = rowBase + r;
            const __nv_bfloat16* asrc = &As[(size_t)(grow < M ? grow : 0) * K + kOff + kseg * 8];
            CP_ASYNC16(aSt + doff, asrc, (grow < M) ? 16 : 0);
            CP_ASYNC16(wSt + doff, &Ws[(size_t)(colBase + r) * K + kOff + kseg * 8], 16);
        }
        CP_COMMIT();
    };

    issue(0, 0, 0);
    CP_WAIT0();
    __syncthreads();

    int buf = 0;
    for (int ch = 0; ch < chunks; ch++) {
        const bool hasNext = (ch + 1 < chunks);
        if (hasNext) {
            const int nc = ch + 1;
            issue(buf ^ 1, nc % 3, nc / 3);
        }

        const uint32_t aBase = sBase + buf * STAGE_BYTES;
        const uint32_t bBase = sBase + ABUF_BYTES + buf * STAGE_BYTES;
#pragma unroll
        for (int ks = 0; ks < 4; ks++) {
            uint32_t a[4][4];
#pragma unroll
            for (int mi = 0; mi < 4; mi++) {
                int r = wr * 64 + mi * 16 + aRowL;
                uint32_t seg = (uint32_t)((ks * 2 + aSegH) ^ (r & 7));
                ldsm_x4(a[mi], aBase + (uint32_t)(r * 128) + (seg << 4));
            }
#pragma unroll
            for (int nj2 = 0; nj2 < 4; nj2++) {
                uint32_t b[4];
                int r = wc * 64 + nj2 * 16 + bRowL;
                uint32_t seg = (uint32_t)((ks * 2 + bSegH) ^ (r & 7));
                ldsm_x4(b, bBase + (uint32_t)(r * 128) + (seg << 4));
#pragma unroll
                for (int mi = 0; mi < 4; mi++) {
                    mma16816(acc[mi][nj2 * 2 + 0], a[mi], b[0], b[1]);
                    mma16816(acc[mi][nj2 * 2 + 1], a[mi], b[2], b[3]);
                }
            }
        }

        if (hasNext) {
            CP_WAIT0();
            __syncthreads();
            buf ^= 1;
        }
    }

    // ---- epilogue: +bias, store ----
    const int rBase0 = rowBase + wr * 64 + (lane >> 2);
    const int cBase  = colBase + wc * 64 + ((lane & 3) << 1);
#pragma unroll
    for (int mi = 0; mi < 4; mi++) {
        int r0 = rBase0 + mi * 16;
        int r1 = r0 + 8;
#pragma unroll
        for (int nj = 0; nj < 8; nj++) {
            int col = cBase + nj * 8;
            float2 b2 = *(const float2*)&biascat[col];
            if (r0 < M) {
                float2 o = make_float2(acc[mi][nj][0] + b2.x, acc[mi][nj][1] + b2.y);
                *(float2*)&C[(size_t)r0 * Ncat + col] = o;
            }
            if (r1 < M) {
                float2 o = make_float2(acc[mi][nj][2] + b2.x, acc[mi][nj][3] + b2.y);
                *(float2*)&C[(size_t)r1 * Ncat + col] = o;
            }
        }
    }
}

// ----------------------------------------------------------------------------
// CSR aggregation, no atomics. thread = (dst node, float4 chunk).
//   acc = skip[n] (cat +3D); for each in-edge j: acc += sigmoid(k[n]+q[j])*v[j]
//   store H; optionally emit bf16 hi/lo for next layer's GEMM input.
// ----------------------------------------------------------------------------
__global__ void edge_agg(const int* __restrict__ off, const int* __restrict__ srcs,
                         float* __restrict__ cat,
                         __nv_bfloat16* __restrict__ hiOut, __nv_bfloat16* __restrict__ loOut,
                         int Nn, int D, int stride, int cshift)
{
    int idx = blockIdx.x * blockDim.x + threadIdx.x;
    int total = Nn << cshift;
    if (idx >= total) return;
    int n = idx >> cshift;
    int c = (idx & ((1 << cshift) - 1)) << 2;
    const int D2 = 2 * D, D3 = 3 * D;

    const float4 k = *(const float4*)&cat[(size_t)n * stride + c];
    float4 acc     = *(const float4*)&cat[(size_t)n * stride + D3 + c];

    const int s0 = off[n], s1 = off[n + 1];
#pragma unroll 2
    for (int i = s0; i < s1; i++) {
        int s = srcs[i];
        const float4 q = *(const float4*)&cat[(size_t)s * stride + D + c];
        const float4 v = *(const float4*)&cat[(size_t)s * stride + D2 + c];
        acc.x += v.x / (1.f + __expf(-(k.x + q.x)));
        acc.y += v.y / (1.f + __expf(-(k.y + q.y)));
        acc.z += v.z / (1.f + __expf(-(k.z + q.z)));
        acc.w += v.w / (1.f + __expf(-(k.w + q.w)));
    }

    *(float4*)&cat[(size_t)n * stride + D3 + c] = acc;

    if (hiOut) {
        __nv_bfloat16 h[4], l[4];
        const float* af = (const float*)&acc;
#pragma unroll
        for (int j = 0; j < 4; j++) {
            h[j] = __float2bfloat16(af[j]);
            l[j] = __float2bfloat16(af[j] - __bfloat162float(h[j]));
        }
        *(uint2*)&hiOut[(size_t)n * D + c] = *(const uint2*)h;
        *(uint2*)&loOut[(size_t)n * D + c] = *(const uint2*)l;
    }
}

// ----------------------------------------------------------------------------
// Row softmax over 64 cols (strided source): one warp per row.
// ----------------------------------------------------------------------------
__global__ void softmax64(const float* __restrict__ H, int stride, int offc,
                          float* __restrict__ out, int M)
{
    int warp = threadIdx.x >> 5;
    int lane = threadIdx.x & 31;
    int row  = blockIdx.x * (blockDim.x >> 5) + warp;
    if (row >= M) return;
    float a = H[(size_t)row * stride + offc + lane];
    float b = H[(size_t)row * stride + offc + 32 + lane];
    float mx = fmaxf(a, b);
#pragma unroll
    for (int o = 16; o > 0; o >>= 1) mx = fmaxf(mx, __shfl_xor_sync(0xffffffffu, mx, o));
    float ea = __expf(a - mx);
    float eb = __expf(b - mx);
    float s  = ea + eb;
#pragma unroll
    for (int o = 16; o > 0; o >>= 1) s += __shfl_xor_sync(0xffffffffu, s, o);
    float inv = 1.f / s;
    out[row * 64 + lane]      = ea * inv;
    out[row * 64 + 32 + lane] = eb * inv;
}

// ----------------------------------------------------------------------------
extern "C" void kernel_launch(void* const* d_in, const int* in_sizes, int n_in,
                              void* d_out, int out_size)
{
    const float* x  = (const float*)d_in[0];
    const void*  ei = d_in[1];
    const int Nn = in_sizes[0] / 256;
    const int E  = in_sizes[1] / 2;

    float *pCat, *pBias;
    __nv_bfloat16 *pAhi, *pAlo, *pWhi, *pWlo;
    int *pOff, *pCur, *pSrcs, *pBsum;
    cudaGetSymbolAddress((void**)&pCat,  g_cat);
    cudaGetSymbolAddress((void**)&pAhi,  g_Ahi);
    cudaGetSymbolAddress((void**)&pAlo,  g_Alo);
    cudaGetSymbolAddress((void**)&pWhi,  g_Whi);
    cudaGetSymbolAddress((void**)&pWlo,  g_Wlo);
    cudaGetSymbolAddress((void**)&pBias, g_bias);
    cudaGetSymbolAddress((void**)&pOff,  g_off);
    cudaGetSymbolAddress((void**)&pCur,  g_cur);
    cudaGetSymbolAddress((void**)&pSrcs, g_srcs);
    cudaGetSymbolAddress((void**)&pBsum, g_bsum);

    const float* w[26];
    for (int i = 2; i < 26; i++) w[i] = (const float*)d_in[i];

    const int gm = (Nn + 127) / 128;
    const int SMEM = 2 * ABUF_BYTES;   // 64 KB
    cudaFuncSetAttribute(gemm_mma, cudaFuncAttributeMaxDynamicSharedMemorySize, SMEM);

    // ---- CSR build (once per call, reused by all 3 layers) ----
    const int nb = (Nn + 1023) / 1024;   // 20 scan blocks (<= 64)
    detect_i64<<<1, 256>>>((const unsigned int*)ei);
    zero_i<<<(Nn + 255) / 256, 256>>>(pCur, Nn);
    build_hist<<<(E + 255) / 256, 256>>>(ei, pCur, E);
    scan_p1<<<nb, 1024>>>(pCur, pBsum, Nn);
    scan_p2<<<1, 32>>>(pBsum, pOff, nb, Nn);
    scan_p3<<<nb, 1024>>>(pCur, pBsum, pOff, pCur, Nn);  // overwrites cur w/ cursors
    build_csr<<<(E + 255) / 256, 256>>>(ei, pCur, pSrcs, E);

    // ---- layer 1: K=256, D=256, Ncat=1024 ----
    conv_w<<<(1024 * 256 + 255) / 256, 256>>>(
        w[2], w[4], w[6], w[20], w[3], w[5], w[7], w[21],
        pWhi, pWlo, pBias, 256, 256);
    conv_a<<<(Nn * 256 + 255) / 256, 256>>>(x, pAhi, pAlo, Nn * 256);
    gemm_mma<<<dim3(gm, 8), 128, SMEM>>>(pAhi, pAlo, pWhi, pWlo, pBias, pCat, Nn, 256, 1024);
    edge_agg<<<((Nn << 6) + 255) / 256, 256>>>(pOff, pSrcs, pCat, pAhi, pAlo, Nn, 256, 1024, 6);

    // ---- layer 2: K=256, D=128, Ncat=512 ----
    conv_w<<<(512 * 256 + 255) / 256, 256>>>(
        w[8], w[10], w[12], w[22], w[9], w[11], w[13], w[23],
        pWhi, pWlo, pBias, 256, 128);
    gemm_mma<<<dim3(gm, 4), 128, SMEM>>>(pAhi, pAlo, pWhi, pWlo, pBias, pCat, Nn, 256, 512);
    edge_agg<<<((Nn << 5) + 255) / 256, 256>>>(pOff, pSrcs, pCat, pAhi, pAlo, Nn, 128, 512, 5);

    // ---- layer 3: K=128, D=64, Ncat=256 ----
    conv_w<<<(256 * 128 + 255) / 256, 256>>>(
        w[14], w[16], w[18], w[24], w[15], w[17], w[19], w[25],
        pWhi, pWlo, pBias, 128, 64);
    gemm_mma<<<dim3(gm, 2), 128, SMEM>>>(pAhi, pAlo, pWhi, pWlo, pBias, pCat, Nn, 128, 256);
    edge_agg<<<((Nn << 4) + 255) / 256, 256>>>(pOff, pSrcs, pCat, nullptr, nullptr, Nn, 64, 256, 4);

    softmax64<<<(Nn + 7) / 8, 256>>>(pCat, 256, 192, (float*)d_out, Nn);
}

// round 16
// speedup vs baseline: 1.1377x; 1.0844x over previous
#include <cuda_runtime.h>
#include <cuda_bf16.h>
#include <cstdint>

// ============================================================================
// ResGatedGraphConv x3 + softmax. GEMMs on mma.sync bf16 (split-precision).
//   per layer: cat = A @ [Wk|Wq|Wv|Ws]^T + [bk|bq|bv|bias]  (one fused GEMM)
//              H[n] = skip[n] + sum_{j->n} sigmoid(K[n]+Q[j]) * V[j]
// CSR (counting sort by dst) aggregation -> no atomics.
// Multi-stream fork-join capture: CSR build + conv_w(2,3) overlap gemm1 chain.
// Layer-3 aggregation fuses the row softmax (subwarp shfl) -> writes d_out.
// ============================================================================

#define NMAX 20000
#define EMAX 400000

__device__ float         g_cat  [NMAX * 1024];  // per-layer [N, 4D]: K|Q|V|H
__device__ __nv_bfloat16 g_Ahi  [NMAX * 256];
__device__ __nv_bfloat16 g_Alo  [NMAX * 256];
__device__ __nv_bfloat16 g_Whi1 [1024 * 256];
__device__ __nv_bfloat16 g_Wlo1 [1024 * 256];
__device__ __nv_bfloat16 g_Whi2 [512 * 256];
__device__ __nv_bfloat16 g_Wlo2 [512 * 256];
__device__ __nv_bfloat16 g_Whi3 [256 * 128];
__device__ __nv_bfloat16 g_Wlo3 [256 * 128];
__device__ float         g_bias1[1024];
__device__ float         g_bias2[512];
__device__ float         g_bias3[256];
__device__ int           g_is64;
__device__ int           g_off [NMAX + 1];
__device__ int           g_cur [NMAX];
__device__ int           g_srcs[EMAX];
__device__ int           g_bsum[64];

__device__ __forceinline__ uint32_t smem_u32(const void* p) {
    uint32_t a;
    asm("{ .reg .u64 t; cvta.to.shared.u64 t, %1; cvt.u32.u64 %0, t; }" : "=r"(a) : "l"(p));
    return a;
}

__device__ __forceinline__ void ldsm_x4(uint32_t* r, uint32_t addr) {
    asm volatile("ldmatrix.sync.aligned.m8n8.x4.shared.b16 {%0,%1,%2,%3}, [%4];"
                 : "=r"(r[0]), "=r"(r[1]), "=r"(r[2]), "=r"(r[3]) : "r"(addr));
}

__device__ __forceinline__ void mma16816(float* c, const uint32_t* a,
                                         uint32_t b0, uint32_t b1) {
    asm volatile(
        "mma.sync.aligned.m16n8k16.row.col.f32.bf16.bf16.f32 "
        "{%0,%1,%2,%3}, {%4,%5,%6,%7}, {%8,%9}, {%0,%1,%2,%3};"
        : "+f"(c[0]), "+f"(c[1]), "+f"(c[2]), "+f"(c[3])
        : "r"(a[0]), "r"(a[1]), "r"(a[2]), "r"(a[3]), "r"(b0), "r"(b1));
}

#define CP_ASYNC16(dst, src, sz) \
    asm volatile("cp.async.cg.shared.global [%0], [%1], 16, %2;" \
                 :: "r"(dst), "l"(src), "r"(sz))
#define CP_COMMIT()  asm volatile("cp.async.commit_group;" ::: "memory")
#define CP_WAIT0()   asm volatile("cp.async.wait_group 0;" ::: "memory")

// ----------------------------------------------------------------------------
// zero cur[] + (block 0) edge_index dtype detection
// ----------------------------------------------------------------------------
__global__ void zero_detect(const unsigned int* __restrict__ ei_u32,
                            int* __restrict__ cur, int Nn) {
    int i = blockIdx.x * blockDim.x + threadIdx.x;
    if (i < Nn) cur[i] = 0;
    if (blockIdx.x == 0) {
        __shared__ unsigned int s;
        if (threadIdx.x == 0) s = 0u;
        __syncthreads();
        unsigned int v = 0u;
        for (int j = threadIdx.x; j < 2048; j += blockDim.x) v |= ei_u32[2 * j + 1];
        atomicOr(&s, v);
        __syncthreads();
        if (threadIdx.x == 0) g_is64 = (s == 0u) ? 1 : 0;
    }
}

__global__ void build_hist(const void* __restrict__ ei_raw, int* __restrict__ deg, int E) {
    int e = blockIdx.x * blockDim.x + threadIdx.x;
    if (e >= E) return;
    int dst = g_is64 ? (int)((const long long*)ei_raw)[E + e]
                     : ((const int*)ei_raw)[E + e];
    atomicAdd(&deg[dst], 1);
}

// pass 1: per-block (1024 elems) sum, coalesced
__global__ void scan_p1(const int* __restrict__ deg, int* __restrict__ bsum, int Nn) {
    __shared__ int wsum[32];
    int g = blockIdx.x * 1024 + threadIdx.x;
    int v = (g < Nn) ? deg[g] : 0;
    int s = v;
#pragma unroll
    for (int o = 16; o > 0; o >>= 1) s += __shfl_xor_sync(0xffffffffu, s, o);
    if ((threadIdx.x & 31) == 0) wsum[threadIdx.x >> 5] = s;
    __syncthreads();
    if (threadIdx.x < 32) {
        int t = wsum[threadIdx.x];
#pragma unroll
        for (int o = 16; o > 0; o >>= 1) t += __shfl_xor_sync(0xffffffffu, t, o);
        if (threadIdx.x == 0) bsum[blockIdx.x] = t;
    }
}

// pass 2 (fused): each block re-scans bsum locally (nb <= 32) + local scan
__global__ void scan_p3f(const int* __restrict__ deg, const int* __restrict__ bsum,
                         int* __restrict__ off, int* __restrict__ cur, int Nn, int nb) {
    __shared__ int wtot[32];
    __shared__ int sbase[32];
    __shared__ int stot;
    int g = blockIdx.x * 1024 + threadIdx.x;
    int lane = threadIdx.x & 31;
    int wrp  = threadIdx.x >> 5;
    int v = (g < Nn) ? deg[g] : 0;
    int inc = v;
#pragma unroll
    for (int o = 1; o < 32; o <<= 1) {
        int u = __shfl_up_sync(0xffffffffu, inc, o);
        if (lane >= o) inc += u;
    }
    if (lane == 31) wtot[wrp] = inc;
    __syncthreads();
    if (wrp == 0) {
        int t = wtot[lane];
        int wi = t;
#pragma unroll
        for (int o = 1; o < 32; o <<= 1) {
            int u = __shfl_up_sync(0xffffffffu, wi, o);
            if (lane >= o) wi += u;
        }
        wtot[lane] = wi - t;
    } else if (wrp == 1) {
        int b = (lane < nb) ? bsum[lane] : 0;
        int bi = b;
#pragma unroll
        for (int o = 1; o < 32; o <<= 1) {
            int u = __shfl_up_sync(0xffffffffu, bi, o);
            if (lane >= o) bi += u;
        }
        sbase[lane] = bi - b;
        if (lane == 31) stot = bi;
    }
    __syncthreads();
    if (g < Nn) {
        int ex = sbase[blockIdx.x] + wtot[wrp] + inc - v;
        off[g] = ex;
        cur[g] = ex;
    }
    if (blockIdx.x == 0 && threadIdx.x == 0) off[Nn] = stot;
}

__global__ void build_csr(const void* __restrict__ ei_raw, int* __restrict__ cur,
                          int* __restrict__ srcs, int E) {
    int e = blockIdx.x * blockDim.x + threadIdx.x;
    if (e >= E) return;
    int src, dst;
    if (g_is64) {
        const long long* ei = (const long long*)ei_raw;
        src = (int)ei[e];
        dst = (int)ei[E + e];
    } else {
        const int* ei = (const int*)ei_raw;
        src = ei[e];
        dst = ei[E + e];
    }
    int pos = atomicAdd(&cur[dst], 1);
    srcs[pos] = src;
}

// ----------------------------------------------------------------------------
// Activation convert (layer 1 only): fp32 -> bf16 hi/lo
// ----------------------------------------------------------------------------
__global__ void conv_a(const float* __restrict__ src,
                       __nv_bfloat16* __restrict__ hi, __nv_bfloat16* __restrict__ lo,
                       int total)
{
    int idx = blockIdx.x * blockDim.x + threadIdx.x;
    if (idx >= total) return;
    float a = src[idx];
    __nv_bfloat16 h = __float2bfloat16(a);
    hi[idx] = h;
    lo[idx] = __float2bfloat16(a - __bfloat162float(h));
}

// ----------------------------------------------------------------------------
// Weight convert: 4x W [K, D] fp32 -> transposed concat [Ncat=4D, K] bf16 hi/lo
// ----------------------------------------------------------------------------
__global__ void conv_w(const float* __restrict__ W0, const float* __restrict__ W1,
                       const float* __restrict__ W2, const float* __restrict__ W3,
                       const float* __restrict__ b0, const float* __restrict__ b1,
                       const float* __restrict__ b2, const float* __restrict__ b3,
                       __nv_bfloat16* __restrict__ hi, __nv_bfloat16* __restrict__ lo,
                       float* __restrict__ biascat, int K, int D)
{
    int idx = blockIdx.x * blockDim.x + threadIdx.x;
    int Ncat = 4 * D;
    if (idx >= Ncat * K) return;
    int n = idx / K, k = idx - n * K;
    int z = n / D, jz = n - z * D;
    const float* W = (z == 0) ? W0 : (z == 1) ? W1 : (z == 2) ? W2 : W3;
    float w = W[(size_t)k * D + jz];
    __nv_bfloat16 h = __float2bfloat16(w);
    hi[idx] = h;
    lo[idx] = __float2bfloat16(w - __bfloat162float(h));
    if (k == 0) {
        const float* b = (z == 0) ? b0 : (z == 1) ? b1 : (z == 2) ? b2 : b3;
        biascat[n] = b[jz];
    }
}

// ----------------------------------------------------------------------------
// mma.sync GEMM: cat[M, Ncat] = Ahi@Whi^T + Ahi@Wlo^T + Alo@Whi^T + bias
//   128 threads / 4 warps (2x2), CTA 128x128, warp 64x64, BK=64,
//   XOR-swizzled smem, 2-stage cp.async pipeline (dynamic smem 64 KB).
// ----------------------------------------------------------------------------
#define STAGE_BYTES 16384          // 128 rows * 128 B
#define ABUF_BYTES  (2 * STAGE_BYTES)

__global__ __launch_bounds__(128)
void gemm_mma(const __nv_bfloat16* __restrict__ Ahi, const __nv_bfloat16* __restrict__ Alo,
              const __nv_bfloat16* __restrict__ Whi, const __nv_bfloat16* __restrict__ Wlo,
              const float* __restrict__ biascat, float* __restrict__ C,
              int M, int K, int Ncat)
{
    extern __shared__ __align__(1024) char dynsmem[];

    const int tid  = threadIdx.x;
    const int wid  = tid >> 5;
    const int lane = tid & 31;
    const int wr   = wid & 1;
    const int wc   = wid >> 1;
    const int rowBase = blockIdx.x * 128;
    const int colBase = blockIdx.y * 128;

    const uint32_t sBase = smem_u32(dynsmem);

    const int aRowL = (lane & 15);
    const int aSegH = (lane >> 4);
    const int grp   = lane >> 3;
    const int bRowL = (grp >> 1) * 8 + (lane & 7);
    const int bSegH = (grp & 1);

    float acc[4][8][4];
#pragma unroll
    for (int mi = 0; mi < 4; mi++)
#pragma unroll
        for (int nj = 0; nj < 8; nj++)
#pragma unroll
            for (int q = 0; q < 4; q++) acc[mi][nj][q] = 0.f;

    const int chunks = 3 * (K >> 6);

    auto issue = [&](int stage, int p, int kc) {
        const __nv_bfloat16* __restrict__ As = (p == 2) ? Alo : Ahi;
        const __nv_bfloat16* __restrict__ Ws = (p == 1) ? Wlo : Whi;
        const int kOff = kc << 6;
        const uint32_t aSt = sBase + stage * STAGE_BYTES;
        const uint32_t wSt = sBase + ABUF_BYTES + stage * STAGE_BYTES;
#pragma unroll
        for (int it = 0; it < 8; it++) {
            int idx  = it * 128 + tid;
            int r    = idx >> 3;
            int kseg = idx & 7;
            uint32_t doff = (uint32_t)(r * 128 + ((kseg ^ (r & 7)) << 4));
            int grow = rowBase + r;
            const __nv_bfloat16* asrc = &As[(size_t)(grow < M ? grow : 0) * K + kOff + kseg * 8];
            CP_ASYNC16(aSt + doff, asrc, (grow < M) ? 16 : 0);
            CP_ASYNC16(wSt + doff, &Ws[(size_t)(colBase + r) * K + kOff + kseg * 8], 16);
        }
        CP_COMMIT();
    };

    issue(0, 0, 0);
    CP_WAIT0();
    __syncthreads();

    int buf = 0;
    for (int ch = 0; ch < chunks; ch++) {
        const bool hasNext = (ch + 1 < chunks);
        if (hasNext) {
            const int nc = ch + 1;
            issue(buf ^ 1, nc % 3, nc / 3);
        }

        const uint32_t aBase = sBase + buf * STAGE_BYTES;
        const uint32_t bBase = sBase + ABUF_BYTES + buf * STAGE_BYTES;
#pragma unroll
        for (int ks = 0; ks < 4; ks++) {
            uint32_t a[4][4];
#pragma unroll
            for (int mi = 0; mi < 4; mi++) {
                int r = wr * 64 + mi * 16 + aRowL;
                uint32_t seg = (uint32_t)((ks * 2 + aSegH) ^ (r & 7));
                ldsm_x4(a[mi], aBase + (uint32_t)(r * 128) + (seg << 4));
            }
#pragma unroll
            for (int nj2 = 0; nj2 < 4; nj2++) {
                uint32_t b[4];
                int r = wc * 64 + nj2 * 16 + bRowL;
                uint32_t seg = (uint32_t)((ks * 2 + bSegH) ^ (r & 7));
                ldsm_x4(b, bBase + (uint32_t)(r * 128) + (seg << 4));
#pragma unroll
                for (int mi = 0; mi < 4; mi++) {
                    mma16816(acc[mi][nj2 * 2 + 0], a[mi], b[0], b[1]);
                    mma16816(acc[mi][nj2 * 2 + 1], a[mi], b[2], b[3]);
                }
            }
        }

        if (hasNext) {
            CP_WAIT0();
            __syncthreads();
            buf ^= 1;
        }
    }

    // ---- epilogue: +bias, store ----
    const int rBase0 = rowBase + wr * 64 + (lane >> 2);
    const int cBase  = colBase + wc * 64 + ((lane & 3) << 1);
#pragma unroll
    for (int mi = 0; mi < 4; mi++) {
        int r0 = rBase0 + mi * 16;
        int r1 = r0 + 8;
#pragma unroll
        for (int nj = 0; nj < 8; nj++) {
            int col = cBase + nj * 8;
            float2 b2 = *(const float2*)&biascat[col];
            if (r0 < M) {
                float2 o = make_float2(acc[mi][nj][0] + b2.x, acc[mi][nj][1] + b2.y);
                *(float2*)&C[(size_t)r0 * Ncat + col] = o;
            }
            if (r1 < M) {
                float2 o = make_float2(acc[mi][nj][2] + b2.x, acc[mi][nj][3] + b2.y);
                *(float2*)&C[(size_t)r1 * Ncat + col] = o;
            }
        }
    }
}

// ----------------------------------------------------------------------------
// CSR aggregation (layers 1-2), no atomics. thread = (dst node, float4 chunk).
// ----------------------------------------------------------------------------
__global__ void edge_agg(const int* __restrict__ off, const int* __restrict__ srcs,
                         float* __restrict__ cat,
                         __nv_bfloat16* __restrict__ hiOut, __nv_bfloat16* __restrict__ loOut,
                         int Nn, int D, int stride, int cshift)
{
    int idx = blockIdx.x * blockDim.x + threadIdx.x;
    int total = Nn << cshift;
    if (idx >= total) return;
    int n = idx >> cshift;
    int c = (idx & ((1 << cshift) - 1)) << 2;
    const int D2 = 2 * D, D3 = 3 * D;

    const float4 k = *(const float4*)&cat[(size_t)n * stride + c];
    float4 acc     = *(const float4*)&cat[(size_t)n * stride + D3 + c];

    const int s0 = off[n], s1 = off[n + 1];
#pragma unroll 2
    for (int i = s0; i < s1; i++) {
        int s = srcs[i];
        const float4 q = *(const float4*)&cat[(size_t)s * stride + D + c];
        const float4 v = *(const float4*)&cat[(size_t)s * stride + D2 + c];
        acc.x += v.x / (1.f + __expf(-(k.x + q.x)));
        acc.y += v.y / (1.f + __expf(-(k.y + q.y)));
        acc.z += v.z / (1.f + __expf(-(k.z + q.z)));
        acc.w += v.w / (1.f + __expf(-(k.w + q.w)));
    }

    *(float4*)&cat[(size_t)n * stride + D3 + c] = acc;

    __nv_bfloat16 h[4], l[4];
    const float* af = (const float*)&acc;
#pragma unroll
    for (int j = 0; j < 4; j++) {
        h[j] = __float2bfloat16(af[j]);
        l[j] = __float2bfloat16(af[j] - __bfloat162float(h[j]));
    }
    *(uint2*)&hiOut[(size_t)n * D + c] = *(const uint2*)h;
    *(uint2*)&loOut[(size_t)n * D + c] = *(const uint2*)l;
}

// ----------------------------------------------------------------------------
// Layer-3 aggregation + fused row softmax (D=64, stride=256, 16 thr/node).
// Total threads Nn*16 is a multiple of 32 -> no partial warps; shfl offsets
// <= 8 stay within each aligned 16-lane node group.
// ----------------------------------------------------------------------------
__global__ void edge_agg_sm(const int* __restrict__ off, const int* __restrict__ srcs,
                            const float* __restrict__ cat, float* __restrict__ out,
                            int Nn)
{
    int idx = blockIdx.x * blockDim.x + threadIdx.x;
    if (idx >= Nn * 16) return;
    int n = idx >> 4;
    int c = (idx & 15) << 2;

    const float4 k = *(const float4*)&cat[(size_t)n * 256 + c];
    float4 acc     = *(const float4*)&cat[(size_t)n * 256 + 192 + c];

    const int s0 = off[n], s1 = off[n + 1];
#pragma unroll 2
    for (int i = s0; i < s1; i++) {
        int s = srcs[i];
        const float4 q = *(const float4*)&cat[(size_t)s * 256 + 64 + c];
        const float4 v = *(const float4*)&cat[(size_t)s * 256 + 128 + c];
        acc.x += v.x / (1.f + __expf(-(k.x + q.x)));
        acc.y += v.y / (1.f + __expf(-(k.y + q.y)));
        acc.z += v.z / (1.f + __expf(-(k.z + q.z)));
        acc.w += v.w / (1.f + __expf(-(k.w + q.w)));
    }

    // softmax over the 64-col row (16-lane group)
    float mx = fmaxf(fmaxf(acc.x, acc.y), fmaxf(acc.z, acc.w));
#pragma unroll
    for (int o = 8; o > 0; o >>= 1) mx = fmaxf(mx, __shfl_xor_sync(0xffffffffu, mx, o));
    float e0 = __expf(acc.x - mx);
    float e1 = __expf(acc.y - mx);
    float e2 = __expf(acc.z - mx);
    float e3 = __expf(acc.w - mx);
    float s = e0 + e1 + e2 + e3;
#pragma unroll
    for (int o = 8; o > 0; o >>= 1) s += __shfl_xor_sync(0xffffffffu, s, o);
    float inv = 1.f / s;
    float4 o4 = make_float4(e0 * inv, e1 * inv, e2 * inv, e3 * inv);
    *(float4*)&out[(size_t)n * 64 + c] = o4;
}

// ----------------------------------------------------------------------------
struct SideRes {
    cudaStream_t s2, s3;
    cudaEvent_t  e0, eCSR, eW;
    SideRes() {
        cudaStreamCreateWithFlags(&s2, cudaStreamNonBlocking);
        cudaStreamCreateWithFlags(&s3, cudaStreamNonBlocking);
        cudaEventCreateWithFlags(&e0,   cudaEventDisableTiming);
        cudaEventCreateWithFlags(&eCSR, cudaEventDisableTiming);
        cudaEventCreateWithFlags(&eW,   cudaEventDisableTiming);
    }
};
static SideRes& SR() { static SideRes r; return r; }

extern "C" void kernel_launch(void* const* d_in, const int* in_sizes, int n_in,
                              void* d_out, int out_size)
{
    const float* x  = (const float*)d_in[0];
    const void*  ei = d_in[1];
    const int Nn = in_sizes[0] / 256;
    const int E  = in_sizes[1] / 2;

    float *pCat, *pB1, *pB2, *pB3;
    __nv_bfloat16 *pAhi, *pAlo, *pWhi1, *pWlo1, *pWhi2, *pWlo2, *pWhi3, *pWlo3;
    int *pOff, *pCur, *pSrcs, *pBsum;
    cudaGetSymbolAddress((void**)&pCat,  g_cat);
    cudaGetSymbolAddress((void**)&pAhi,  g_Ahi);
    cudaGetSymbolAddress((void**)&pAlo,  g_Alo);
    cudaGetSymbolAddress((void**)&pWhi1, g_Whi1);
    cudaGetSymbolAddress((void**)&pWlo1, g_Wlo1);
    cudaGetSymbolAddress((void**)&pWhi2, g_Whi2);
    cudaGetSymbolAddress((void**)&pWlo2, g_Wlo2);
    cudaGetSymbolAddress((void**)&pWhi3, g_Whi3);
    cudaGetSymbolAddress((void**)&pWlo3, g_Wlo3);
    cudaGetSymbolAddress((void**)&pB1,   g_bias1);
    cudaGetSymbolAddress((void**)&pB2,   g_bias2);
    cudaGetSymbolAddress((void**)&pB3,   g_bias3);
    cudaGetSymbolAddress((void**)&pOff,  g_off);
    cudaGetSymbolAddress((void**)&pCur,  g_cur);
    cudaGetSymbolAddress((void**)&pSrcs, g_srcs);
    cudaGetSymbolAddress((void**)&pBsum, g_bsum);

    const float* w[26];
    for (int i = 2; i < 26; i++) w[i] = (const float*)d_in[i];

    const int gm = (Nn + 127) / 128;
    const int SMEM = 2 * ABUF_BYTES;   // 64 KB
    cudaFuncSetAttribute(gemm_mma, cudaFuncAttributeMaxDynamicSharedMemorySize, SMEM);

    SideRes& r = SR();

    // ---- fork side streams off the capture (main) stream ----
    cudaEventRecord(r.e0, 0);
    cudaStreamWaitEvent(r.s2, r.e0, 0);
    cudaStreamWaitEvent(r.s3, r.e0, 0);

    // ---- s2: CSR build chain ----
    const int nb = (Nn + 1023) / 1024;   // <= 32
    zero_detect<<<(Nn + 255) / 256, 256, 0, r.s2>>>((const unsigned int*)ei, pCur, Nn);
    build_hist<<<(E + 255) / 256, 256, 0, r.s2>>>(ei, pCur, E);
    scan_p1<<<nb, 1024, 0, r.s2>>>(pCur, pBsum, Nn);
    scan_p3f<<<nb, 1024, 0, r.s2>>>(pCur, pBsum, pOff, pCur, Nn, nb);
    build_csr<<<(E + 255) / 256, 256, 0, r.s2>>>(ei, pCur, pSrcs, E);
    cudaEventRecord(r.eCSR, r.s2);

    // ---- s3: layer 2/3 weight converts ----
    conv_w<<<(512 * 256 + 255) / 256, 256, 0, r.s3>>>(
        w[8], w[10], w[12], w[22], w[9], w[11], w[13], w[23],
        pWhi2, pWlo2, pB2, 256, 128);
    conv_w<<<(256 * 128 + 255) / 256, 256, 0, r.s3>>>(
        w[14], w[16], w[18], w[24], w[15], w[17], w[19], w[25],
        pWhi3, pWlo3, pB3, 128, 64);
    cudaEventRecord(r.eW, r.s3);

    // ---- main: layer 1 chain ----
    conv_w<<<(1024 * 256 + 255) / 256, 256>>>(
        w[2], w[4], w[6], w[20], w[3], w[5], w[7], w[21],
        pWhi1, pWlo1, pB1, 256, 256);
    conv_a<<<(Nn * 256 + 255) / 256, 256>>>(x, pAhi, pAlo, Nn * 256);
    gemm_mma<<<dim3(gm, 8), 128, SMEM>>>(pAhi, pAlo, pWhi1, pWlo1, pB1, pCat, Nn, 256, 1024);

    cudaStreamWaitEvent(0, r.eCSR, 0);   // join CSR before aggregation
    edge_agg<<<((Nn << 6) + 255) / 256, 256>>>(pOff, pSrcs, pCat, pAhi, pAlo, Nn, 256, 1024, 6);

    cudaStreamWaitEvent(0, r.eW, 0);     // join weight converts before layer 2
    gemm_mma<<<dim3(gm, 4), 128, SMEM>>>(pAhi, pAlo, pWhi2, pWlo2, pB2, pCat, Nn, 256, 512);
    edge_agg<<<((Nn << 5) + 255) / 256, 256>>>(pOff, pSrcs, pCat, pAhi, pAlo, Nn, 128, 512, 5);

    gemm_mma<<<dim3(gm, 2), 128, SMEM>>>(pAhi, pAlo, pWhi3, pWlo3, pB3, pCat, Nn, 128, 256);
    edge_agg_sm<<<((Nn << 4) + 255) / 256, 256>>>(pOff, pSrcs, pCat, (float*)d_out, Nn);
}

// round 17
// speedup vs baseline: 1.1587x; 1.0185x over previous
#include <cuda_runtime.h>
#include <cuda_bf16.h>
#include <cuda_fp16.h>
#include <cstdint>

// ============================================================================
// ResGatedGraphConv x3 + softmax. GEMMs on mma.sync bf16 (split-precision).
//   per layer: [K|Q](fp16), [V|H](fp32) = A @ [Wk|Wq|Wv|Ws]^T + biases
//              H[n] = skip[n] + sum_{j->n} sigmoid(K[n]+Q[j]) * V[j]
// CSR (counting sort by dst) aggregation -> no atomics; K/Q gathers fp16
// (sigmoid' damps K/Q rounding; V/H stay fp32). Fork-join multi-stream capture.
// Layer-3 aggregation fuses the row softmax -> writes d_out.
// ============================================================================

#define NMAX 20000
#define EMAX 400000

__device__ __half        g_KQ  [NMAX * 512];    // per-layer [N, 2D] fp16: K|Q
__device__ float         g_VH  [NMAX * 512];    // per-layer [N, 2D] fp32: V|H
__device__ __nv_bfloat16 g_Ahi [NMAX * 256];
__device__ __nv_bfloat16 g_Alo [NMAX * 256];
__device__ __nv_bfloat16 g_Whi1[1024 * 256];
__device__ __nv_bfloat16 g_Wlo1[1024 * 256];
__device__ __nv_bfloat16 g_Whi2[512 * 256];
__device__ __nv_bfloat16 g_Wlo2[512 * 256];
__device__ __nv_bfloat16 g_Whi3[256 * 128];
__device__ __nv_bfloat16 g_Wlo3[256 * 128];
__device__ float         g_bias1[1024];
__device__ float         g_bias2[512];
__device__ float         g_bias3[256];
__device__ int           g_is64;
__device__ int           g_off [NMAX + 1];
__device__ int           g_cur [NMAX];
__device__ int           g_srcs[EMAX];
__device__ int           g_bsum[64];

__device__ __forceinline__ uint32_t smem_u32(const void* p) {
    uint32_t a;
    asm("{ .reg .u64 t; cvta.to.shared.u64 t, %1; cvt.u32.u64 %0, t; }" : "=r"(a) : "l"(p));
    return a;
}

__device__ __forceinline__ void ldsm_x4(uint32_t* r, uint32_t addr) {
    asm volatile("ldmatrix.sync.aligned.m8n8.x4.shared.b16 {%0,%1,%2,%3}, [%4];"
                 : "=r"(r[0]), "=r"(r[1]), "=r"(r[2]), "=r"(r[3]) : "r"(addr));
}

__device__ __forceinline__ void mma16816(float* c, const uint32_t* a,
                                         uint32_t b0, uint32_t b1) {
    asm volatile(
        "mma.sync.aligned.m16n8k16.row.col.f32.bf16.bf16.f32 "
        "{%0,%1,%2,%3}, {%4,%5,%6,%7}, {%8,%9}, {%0,%1,%2,%3};"
        : "+f"(c[0]), "+f"(c[1]), "+f"(c[2]), "+f"(c[3])
        : "r"(a[0]), "r"(a[1]), "r"(a[2]), "r"(a[3]), "r"(b0), "r"(b1));
}

#define CP_ASYNC16(dst, src, sz) \
    asm volatile("cp.async.cg.shared.global [%0], [%1], 16, %2;" \
                 :: "r"(dst), "l"(src), "r"(sz))
#define CP_COMMIT()  asm volatile("cp.async.commit_group;" ::: "memory")
#define CP_WAIT0()   asm volatile("cp.async.wait_group 0;" ::: "memory")

// ----------------------------------------------------------------------------
// zero cur[] + (block 0) edge_index dtype detection
// ----------------------------------------------------------------------------
__global__ void zero_detect(const unsigned int* __restrict__ ei_u32,
                            int* __restrict__ cur, int Nn) {
    int i = blockIdx.x * blockDim.x + threadIdx.x;
    if (i < Nn) cur[i] = 0;
    if (blockIdx.x == 0) {
        __shared__ unsigned int s;
        if (threadIdx.x == 0) s = 0u;
        __syncthreads();
        unsigned int v = 0u;
        for (int j = threadIdx.x; j < 2048; j += blockDim.x) v |= ei_u32[2 * j + 1];
        atomicOr(&s, v);
        __syncthreads();
        if (threadIdx.x == 0) g_is64 = (s == 0u) ? 1 : 0;
    }
}

__global__ void build_hist(const void* __restrict__ ei_raw, int* __restrict__ deg, int E) {
    int e = blockIdx.x * blockDim.x + threadIdx.x;
    if (e >= E) return;
    int dst = g_is64 ? (int)((const long long*)ei_raw)[E + e]
                     : ((const int*)ei_raw)[E + e];
    atomicAdd(&deg[dst], 1);
}

__global__ void scan_p1(const int* __restrict__ deg, int* __restrict__ bsum, int Nn) {
    __shared__ int wsum[32];
    int g = blockIdx.x * 1024 + threadIdx.x;
    int v = (g < Nn) ? deg[g] : 0;
    int s = v;
#pragma unroll
    for (int o = 16; o > 0; o >>= 1) s += __shfl_xor_sync(0xffffffffu, s, o);
    if ((threadIdx.x & 31) == 0) wsum[threadIdx.x >> 5] = s;
    __syncthreads();
    if (threadIdx.x < 32) {
        int t = wsum[threadIdx.x];
#pragma unroll
        for (int o = 16; o > 0; o >>= 1) t += __shfl_xor_sync(0xffffffffu, t, o);
        if (threadIdx.x == 0) bsum[blockIdx.x] = t;
    }
}

__global__ void scan_p3f(const int* __restrict__ deg, const int* __restrict__ bsum,
                         int* __restrict__ off, int* __restrict__ cur, int Nn, int nb) {
    __shared__ int wtot[32];
    __shared__ int sbase[32];
    __shared__ int stot;
    int g = blockIdx.x * 1024 + threadIdx.x;
    int lane = threadIdx.x & 31;
    int wrp  = threadIdx.x >> 5;
    int v = (g < Nn) ? deg[g] : 0;
    int inc = v;
#pragma unroll
    for (int o = 1; o < 32; o <<= 1) {
        int u = __shfl_up_sync(0xffffffffu, inc, o);
        if (lane >= o) inc += u;
    }
    if (lane == 31) wtot[wrp] = inc;
    __syncthreads();
    if (wrp == 0) {
        int t = wtot[lane];
        int wi = t;
#pragma unroll
        for (int o = 1; o < 32; o <<= 1) {
            int u = __shfl_up_sync(0xffffffffu, wi, o);
            if (lane >= o) wi += u;
        }
        wtot[lane] = wi - t;
    } else if (wrp == 1) {
        int b = (lane < nb) ? bsum[lane] : 0;
        int bi = b;
#pragma unroll
        for (int o = 1; o < 32; o <<= 1) {
            int u = __shfl_up_sync(0xffffffffu, bi, o);
            if (lane >= o) bi += u;
        }
        sbase[lane] = bi - b;
        if (lane == 31) stot = bi;
    }
    __syncthreads();
    if (g < Nn) {
        int ex = sbase[blockIdx.x] + wtot[wrp] + inc - v;
        off[g] = ex;
        cur[g] = ex;
    }
    if (blockIdx.x == 0 && threadIdx.x == 0) off[Nn] = stot;
}

__global__ void build_csr(const void* __restrict__ ei_raw, int* __restrict__ cur,
                          int* __restrict__ srcs, int E) {
    int e = blockIdx.x * blockDim.x + threadIdx.x;
    if (e >= E) return;
    int src, dst;
    if (g_is64) {
        const long long* ei = (const long long*)ei_raw;
        src = (int)ei[e];
        dst = (int)ei[E + e];
    } else {
        const int* ei = (const int*)ei_raw;
        src = ei[e];
        dst = ei[E + e];
    }
    int pos = atomicAdd(&cur[dst], 1);
    srcs[pos] = src;
}

// ----------------------------------------------------------------------------
// Activation convert (layer 1 only): fp32 -> bf16 hi/lo
// ----------------------------------------------------------------------------
__global__ void conv_a(const float* __restrict__ src,
                       __nv_bfloat16* __restrict__ hi, __nv_bfloat16* __restrict__ lo,
                       int total)
{
    int idx = blockIdx.x * blockDim.x + threadIdx.x;
    if (idx >= total) return;
    float a = src[idx];
    __nv_bfloat16 h = __float2bfloat16(a);
    hi[idx] = h;
    lo[idx] = __float2bfloat16(a - __bfloat162float(h));
}

// ----------------------------------------------------------------------------
// Weight convert: 4x W [K, D] fp32 -> transposed concat [Ncat=4D, K] bf16 hi/lo
// ----------------------------------------------------------------------------
__global__ void conv_w(const float* __restrict__ W0, const float* __restrict__ W1,
                       const float* __restrict__ W2, const float* __restrict__ W3,
                       const float* __restrict__ b0, const float* __restrict__ b1,
                       const float* __restrict__ b2, const float* __restrict__ b3,
                       __nv_bfloat16* __restrict__ hi, __nv_bfloat16* __restrict__ lo,
                       float* __restrict__ biascat, int K, int D)
{
    int idx = blockIdx.x * blockDim.x + threadIdx.x;
    int Ncat = 4 * D;
    if (idx >= Ncat * K) return;
    int n = idx / K, k = idx - n * K;
    int z = n / D, jz = n - z * D;
    const float* W = (z == 0) ? W0 : (z == 1) ? W1 : (z == 2) ? W2 : W3;
    float w = W[(size_t)k * D + jz];
    __nv_bfloat16 h = __float2bfloat16(w);
    hi[idx] = h;
    lo[idx] = __float2bfloat16(w - __bfloat162float(h));
    if (k == 0) {
        const float* b = (z == 0) ? b0 : (z == 1) ? b1 : (z == 2) ? b2 : b3;
        biascat[n] = b[jz];
    }
}

// ----------------------------------------------------------------------------
// mma.sync GEMM: acc[M, Ncat] = Ahi@Whi^T + Ahi@Wlo^T + Alo@Whi^T + bias
// Epilogue: cols [0,2D) -> fp16 KQ [N,2D]; cols [2D,4D) -> fp32 VH [N,2D].
//   128 threads / 4 warps (2x2), CTA 128x128, warp 64x64, BK=64,
//   XOR-swizzled smem, 2-stage cp.async pipeline (dynamic smem 64 KB).
// ----------------------------------------------------------------------------
#define STAGE_BYTES 16384          // 128 rows * 128 B
#define ABUF_BYTES  (2 * STAGE_BYTES)

__global__ __launch_bounds__(128)
void gemm_mma(const __nv_bfloat16* __restrict__ Ahi, const __nv_bfloat16* __restrict__ Alo,
              const __nv_bfloat16* __restrict__ Whi, const __nv_bfloat16* __restrict__ Wlo,
              const float* __restrict__ biascat, __half* __restrict__ KQ,
              float* __restrict__ VH, int M, int K, int Ncat)
{
    extern __shared__ __align__(1024) char dynsmem[];

    const int tid  = threadIdx.x;
    const int wid  = tid >> 5;
    const int lane = tid & 31;
    const int wr   = wid & 1;
    const int wc   = wid >> 1;
    const int rowBase = blockIdx.x * 128;
    const int colBase = blockIdx.y * 128;

    const uint32_t sBase = smem_u32(dynsmem);

    const int aRowL = (lane & 15);
    const int aSegH = (lane >> 4);
    const int grp   = lane >> 3;
    const int bRowL = (grp >> 1) * 8 + (lane & 7);
    const int bSegH = (grp & 1);

    float acc[4][8][4];
#pragma unroll
    for (int mi = 0; mi < 4; mi++)
#pragma unroll
        for (int nj = 0; nj < 8; nj++)
#pragma unroll
            for (int q = 0; q < 4; q++) acc[mi][nj][q] = 0.f;

    const int chunks = 3 * (K >> 6);

    auto issue = [&](int stage, int p, int kc) {
        const __nv_bfloat16* __restrict__ As = (p == 2) ? Alo : Ahi;
        const __nv_bfloat16* __restrict__ Ws = (p == 1) ? Wlo : Whi;
        const int kOff = kc << 6;
        const uint32_t aSt = sBase + stage * STAGE_BYTES;
        const uint32_t wSt = sBase + ABUF_BYTES + stage * STAGE_BYTES;
#pragma unroll
        for (int it = 0; it < 8; it++) {
            int idx  = it * 128 + tid;
            int r    = idx >> 3;
            int kseg = idx & 7;
            uint32_t doff = (uint32_t)(r * 128 + ((kseg ^ (r & 7)) << 4));
            int grow = rowBase + r;
            const __nv_bfloat16* asrc = &As[(size_t)(grow < M ? grow : 0) * K + kOff + kseg * 8];
            CP_ASYNC16(aSt + doff, asrc, (grow < M) ? 16 : 0);
            CP_ASYNC16(wSt + doff, &Ws[(size_t)(colBase + r) * K + kOff + kseg * 8], 16);
        }
        CP_COMMIT();
    };

    issue(0, 0, 0);
    CP_WAIT0();
    __syncthreads();

    int buf = 0;
    for (int ch = 0; ch < chunks; ch++) {
        const bool hasNext = (ch + 1 < chunks);
        if (hasNext) {
            const int nc = ch + 1;
            issue(buf ^ 1, nc % 3, nc / 3);
        }

        const uint32_t aBase = sBase + buf * STAGE_BYTES;
        const uint32_t bBase = sBase + ABUF_BYTES + buf * STAGE_BYTES;
#pragma unroll
        for (int ks = 0; ks < 4; ks++) {
            uint32_t a[4][4];
#pragma unroll
            for (int mi = 0; mi < 4; mi++) {
                int r = wr * 64 + mi * 16 + aRowL;
                uint32_t seg = (uint32_t)((ks * 2 + aSegH) ^ (r & 7));
                ldsm_x4(a[mi], aBase + (uint32_t)(r * 128) + (seg << 4));
            }
#pragma unroll
            for (int nj2 = 0; nj2 < 4; nj2++) {
                uint32_t b[4];
                int r = wc * 64 + nj2 * 16 + bRowL;
                uint32_t seg = (uint32_t)((ks * 2 + bSegH) ^ (r & 7));
                ldsm_x4(b, bBase + (uint32_t)(r * 128) + (seg << 4));
#pragma unroll
                for (int mi = 0; mi < 4; mi++) {
                    mma16816(acc[mi][nj2 * 2 + 0], a[mi], b[0], b[1]);
                    mma16816(acc[mi][nj2 * 2 + 1], a[mi], b[2], b[3]);
                }
            }
        }

        if (hasNext) {
            CP_WAIT0();
            __syncthreads();
            buf ^= 1;
        }
    }

    // ---- epilogue: +bias; cols < 2D -> fp16 KQ, cols >= 2D -> fp32 VH ----
    const int D2 = Ncat >> 1;
    const int rBase0 = rowBase + wr * 64 + (lane >> 2);
    const int cBase  = colBase + wc * 64 + ((lane & 3) << 1);
#pragma unroll
    for (int mi = 0; mi < 4; mi++) {
        int r0 = rBase0 + mi * 16;
        int r1 = r0 + 8;
#pragma unroll
        for (int nj = 0; nj < 8; nj++) {
            int col = cBase + nj * 8;
            float2 b2 = *(const float2*)&biascat[col];
            float v00 = acc[mi][nj][0] + b2.x, v01 = acc[mi][nj][1] + b2.y;
            float v10 = acc[mi][nj][2] + b2.x, v11 = acc[mi][nj][3] + b2.y;
            if (col < D2) {
                if (r0 < M) *(__half2*)&KQ[(size_t)r0 * D2 + col] = __floats2half2_rn(v00, v01);
                if (r1 < M) *(__half2*)&KQ[(size_t)r1 * D2 + col] = __floats2half2_rn(v10, v11);
            } else {
                int vc = col - D2;
                if (r0 < M) *(float2*)&VH[(size_t)r0 * D2 + vc] = make_float2(v00, v01);
                if (r1 < M) *(float2*)&VH[(size_t)r1 * D2 + vc] = make_float2(v10, v11);
            }
        }
    }
}

// ----------------------------------------------------------------------------
// CSR aggregation (layers 1-2), no atomics. thread = (dst node, float4 chunk).
//   KQ fp16 [N,2D]: K|Q.  VH fp32 [N,2D]: V|skip->H.
//   acc = VH[n, D+c]; for in-edges: acc += sigmoid(K[n]+Q[s]) * V[s]
//   store H; emit bf16 hi/lo for next layer's GEMM input.
// ----------------------------------------------------------------------------
__global__ void edge_agg(const int* __restrict__ off, const int* __restrict__ srcs,
                         const __half* __restrict__ KQ, float* __restrict__ VH,
                         __nv_bfloat16* __restrict__ hiOut, __nv_bfloat16* __restrict__ loOut,
                         int Nn, int D, int cshift)
{
    int idx = blockIdx.x * blockDim.x + threadIdx.x;
    int total = Nn << cshift;
    if (idx >= total) return;
    int n = idx >> cshift;
    int c = (idx & ((1 << cshift) - 1)) << 2;
    const int D2 = 2 * D;

    uint2 ku = *(const uint2*)&KQ[(size_t)n * D2 + c];
    const __half2* kh = (const __half2*)&ku;
    float2 k01 = __half22float2(kh[0]);
    float2 k23 = __half22float2(kh[1]);
    float4 acc = *(const float4*)&VH[(size_t)n * D2 + D + c];

    const int s0 = off[n], s1 = off[n + 1];
#pragma unroll 4
    for (int i = s0; i < s1; i++) {
        int s = srcs[i];
        uint2 qu = *(const uint2*)&KQ[(size_t)s * D2 + D + c];
        const __half2* qh = (const __half2*)&qu;
        float2 q01 = __half22float2(qh[0]);
        float2 q23 = __half22float2(qh[1]);
        const float4 v = *(const float4*)&VH[(size_t)s * D2 + c];
        acc.x += v.x / (1.f + __expf(-(k01.x + q01.x)));
        acc.y += v.y / (1.f + __expf(-(k01.y + q01.y)));
        acc.z += v.z / (1.f + __expf(-(k23.x + q23.x)));
        acc.w += v.w / (1.f + __expf(-(k23.y + q23.y)));
    }

    *(float4*)&VH[(size_t)n * D2 + D + c] = acc;

    __nv_bfloat16 h[4], l[4];
    const float* af = (const float*)&acc;
#pragma unroll
    for (int j = 0; j < 4; j++) {
        h[j] = __float2bfloat16(af[j]);
        l[j] = __float2bfloat16(af[j] - __bfloat162float(h[j]));
    }
    *(uint2*)&hiOut[(size_t)n * D + c] = *(const uint2*)h;
    *(uint2*)&loOut[(size_t)n * D + c] = *(const uint2*)l;
}

// ----------------------------------------------------------------------------
// Layer-3 aggregation + fused row softmax (D=64, 16 thr/node, shfl groups).
// ----------------------------------------------------------------------------
__global__ void edge_agg_sm(const int* __restrict__ off, const int* __restrict__ srcs,
                            const __half* __restrict__ KQ, const float* __restrict__ VH,
                            float* __restrict__ out, int Nn)
{
    int idx = blockIdx.x * blockDim.x + threadIdx.x;
    if (idx >= Nn * 16) return;
    int n = idx >> 4;
    int c = (idx & 15) << 2;

    uint2 ku = *(const uint2*)&KQ[(size_t)n * 128 + c];
    const __half2* kh = (const __half2*)&ku;
    float2 k01 = __half22float2(kh[0]);
    float2 k23 = __half22float2(kh[1]);
    float4 acc = *(const float4*)&VH[(size_t)n * 128 + 64 + c];

    const int s0 = off[n], s1 = off[n + 1];
#pragma unroll 4
    for (int i = s0; i < s1; i++) {
        int s = srcs[i];
        uint2 qu = *(const uint2*)&KQ[(size_t)s * 128 + 64 + c];
        const __half2* qh = (const __half2*)&qu;
        float2 q01 = __half22float2(qh[0]);
        float2 q23 = __half22float2(qh[1]);
        const float4 v = *(const float4*)&VH[(size_t)s * 128 + c];
        acc.x += v.x / (1.f + __expf(-(k01.x + q01.x)));
        acc.y += v.y / (1.f + __expf(-(k01.y + q01.y)));
        acc.z += v.z / (1.f + __expf(-(k23.x + q23.x)));
        acc.w += v.w / (1.f + __expf(-(k23.y + q23.y)));
    }

    // softmax over the 64-col row (16-lane group)
    float mx = fmaxf(fmaxf(acc.x, acc.y), fmaxf(acc.z, acc.w));
#pragma unroll
    for (int o = 8; o > 0; o >>= 1) mx = fmaxf(mx, __shfl_xor_sync(0xffffffffu, mx, o));
    float e0 = __expf(acc.x - mx);
    float e1 = __expf(acc.y - mx);
    float e2 = __expf(acc.z - mx);
    float e3 = __expf(acc.w - mx);
    float s = e0 + e1 + e2 + e3;
#pragma unroll
    for (int o = 8; o > 0; o >>= 1) s += __shfl_xor_sync(0xffffffffu, s, o);
    float inv = 1.f / s;
    float4 o4 = make_float4(e0 * inv, e1 * inv, e2 * inv, e3 * inv);
    *(float4*)&out[(size_t)n * 64 + c] = o4;
}

// ----------------------------------------------------------------------------
struct SideRes {
    cudaStream_t s2, s3;
    cudaEvent_t  e0, eCSR, eW1, eW;
    SideRes() {
        cudaStreamCreateWithFlags(&s2, cudaStreamNonBlocking);
        cudaStreamCreateWithFlags(&s3, cudaStreamNonBlocking);
        cudaEventCreateWithFlags(&e0,   cudaEventDisableTiming);
        cudaEventCreateWithFlags(&eCSR, cudaEventDisableTiming);
        cudaEventCreateWithFlags(&eW1,  cudaEventDisableTiming);
        cudaEventCreateWithFlags(&eW,   cudaEventDisableTiming);
    }
};
static SideRes& SR() { static SideRes r; return r; }

extern "C" void kernel_launch(void* const* d_in, const int* in_sizes, int n_in,
                              void* d_out, int out_size)
{
    const float* x  = (const float*)d_in[0];
    const void*  ei = d_in[1];
    const int Nn = in_sizes[0] / 256;
    const int E  = in_sizes[1] / 2;

    float *pVH, *pB1, *pB2, *pB3;
    __half *pKQ;
    __nv_bfloat16 *pAhi, *pAlo, *pWhi1, *pWlo1, *pWhi2, *pWlo2, *pWhi3, *pWlo3;
    int *pOff, *pCur, *pSrcs, *pBsum;
    cudaGetSymbolAddress((void**)&pKQ,   g_KQ);
    cudaGetSymbolAddress((void**)&pVH,   g_VH);
    cudaGetSymbolAddress((void**)&pAhi,  g_Ahi);
    cudaGetSymbolAddress((void**)&pAlo,  g_Alo);
    cudaGetSymbolAddress((void**)&pWhi1, g_Whi1);
    cudaGetSymbolAddress((void**)&pWlo1, g_Wlo1);
    cudaGetSymbolAddress((void**)&pWhi2, g_Whi2);
    cudaGetSymbolAddress((void**)&pWlo2, g_Wlo2);
    cudaGetSymbolAddress((void**)&pWhi3, g_Whi3);
    cudaGetSymbolAddress((void**)&pWlo3, g_Wlo3);
    cudaGetSymbolAddress((void**)&pB1,   g_bias1);
    cudaGetSymbolAddress((void**)&pB2,   g_bias2);
    cudaGetSymbolAddress((void**)&pB3,   g_bias3);
    cudaGetSymbolAddress((void**)&pOff,  g_off);
    cudaGetSymbolAddress((void**)&pCur,  g_cur);
    cudaGetSymbolAddress((void**)&pSrcs, g_srcs);
    cudaGetSymbolAddress((void**)&pBsum, g_bsum);

    const float* w[26];
    for (int i = 2; i < 26; i++) w[i] = (const float*)d_in[i];

    const int gm = (Nn + 127) / 128;
    const int SMEM = 2 * ABUF_BYTES;   // 64 KB
    cudaFuncSetAttribute(gemm_mma, cudaFuncAttributeMaxDynamicSharedMemorySize, SMEM);

    SideRes& r = SR();

    // ---- fork side streams off the capture (main) stream ----
    cudaEventRecord(r.e0, 0);
    cudaStreamWaitEvent(r.s2, r.e0, 0);
    cudaStreamWaitEvent(r.s3, r.e0, 0);

    // ---- s2: CSR build chain ----
    const int nb = (Nn + 1023) / 1024;   // <= 32
    zero_detect<<<(Nn + 255) / 256, 256, 0, r.s2>>>((const unsigned int*)ei, pCur, Nn);
    build_hist<<<(E + 255) / 256, 256, 0, r.s2>>>(ei, pCur, E);
    scan_p1<<<nb, 1024, 0, r.s2>>>(pCur, pBsum, Nn);
    scan_p3f<<<nb, 1024, 0, r.s2>>>(pCur, pBsum, pOff, pCur, Nn, nb);
    build_csr<<<(E + 255) / 256, 256, 0, r.s2>>>(ei, pCur, pSrcs, E);
    cudaEventRecord(r.eCSR, r.s2);

    // ---- s3: all weight converts (w1 first; overlaps conv_a on main) ----
    conv_w<<<(1024 * 256 + 255) / 256, 256, 0, r.s3>>>(
        w[2], w[4], w[6], w[20], w[3], w[5], w[7], w[21],
        pWhi1, pWlo1, pB1, 256, 256);
    cudaEventRecord(r.eW1, r.s3);
    conv_w<<<(512 * 256 + 255) / 256, 256, 0, r.s3>>>(
        w[8], w[10], w[12], w[22], w[9], w[11], w[13], w[23],
        pWhi2, pWlo2, pB2, 256, 128);
    conv_w<<<(256 * 128 + 255) / 256, 256, 0, r.s3>>>(
        w[14], w[16], w[18], w[24], w[15], w[17], w[19], w[25],
        pWhi3, pWlo3, pB3, 128, 64);
    cudaEventRecord(r.eW, r.s3);

    // ---- main: layer 1 chain ----
    conv_a<<<(Nn * 256 + 255) / 256, 256>>>(x, pAhi, pAlo, Nn * 256);
    cudaStreamWaitEvent(0, r.eW1, 0);
    gemm_mma<<<dim3(gm, 8), 128, SMEM>>>(pAhi, pAlo, pWhi1, pWlo1, pB1, pKQ, pVH, Nn, 256, 1024);

    cudaStreamWaitEvent(0, r.eCSR, 0);   // join CSR before aggregation
    edge_agg<<<((Nn << 6) + 255) / 256, 256>>>(pOff, pSrcs, pKQ, pVH, pAhi, pAlo, Nn, 256, 6);

    cudaStreamWaitEvent(0, r.eW, 0);     // join weight converts before layer 2
    gemm_mma<<<dim3(gm, 4), 128, SMEM>>>(pAhi, pAlo, pWhi2, pWlo2, pB2, pKQ, pVH, Nn, 256, 512);
    edge_agg<<<((Nn << 5) + 255) / 256, 256>>>(pOff, pSrcs, pKQ, pVH, pAhi, pAlo, Nn, 128, 5);

    gemm_mma<<<dim3(gm, 2), 128, SMEM>>>(pAhi, pAlo, pWhi3, pWlo3, pB3, pKQ, pVH, Nn, 128, 256);
    edge_agg_sm<<<((Nn << 4) + 255) / 256, 256>>>(pOff, pSrcs, pKQ, pVH, (float*)d_out, Nn);
}